// round 3
// baseline (speedup 1.0000x reference)
#include <cuda_runtime.h>
#include <cuda_bf16.h>

#define BB 512
#define TT 512
#define LL 128
#define PADL 0
#define BOSL 1
#define EOSL 2

// per-batch (logZ - gold); reduced by second kernel
__device__ float g_res[BB];

// packed f32x2 fma: d = a*b + c on both lanes
__device__ __forceinline__ float2 ffma2(float2 a, float2 b, float2 c) {
    float2 d;
    asm("{\n\t"
        ".reg .b64 ra, rb, rc;\n\t"
        "mov.b64 ra, {%2,%3};\n\t"
        "mov.b64 rb, {%4,%5};\n\t"
        "mov.b64 rc, {%6,%7};\n\t"
        "fma.rn.f32x2 rc, ra, rb, rc;\n\t"
        "mov.b64 {%0,%1}, rc;\n\t"
        "}"
        : "=f"(d.x), "=f"(d.y)
        : "f"(a.x), "f"(a.y), "f"(b.x), "f"(b.y), "f"(c.x), "f"(c.y));
    return d;
}

__global__ __launch_bounds__(128, 2) void crf_fwd(
    const float* __restrict__ feat,   // [B, T, L] f32
    const int* __restrict__ tags,     // [B, T] i32
    const int* __restrict__ mask,     // [B, T] i32 (bool widened by harness)
    const float* __restrict__ tr)     // [L, L] f32
{
    const int j    = threadIdx.x;   // label column 0..127
    const int b0   = blockIdx.x * 2;
    const int b1   = b0 + 1;
    const int lane = j & 31;
    const int wid  = j >> 5;

    __shared__ __align__(16) float u_sh[2][2][LL];  // [buf][batch][i]
    __shared__ float c_sh[2][2];
    __shared__ int   s_len[2];
    __shared__ float s_red[2][4];
    __shared__ float s_gold[2];

    // ---- E column j in registers: E2[k] = (exp(tr[2k][j]), exp(tr[2k+1][j]))
    float2 E2[64];
#pragma unroll
    for (int k = 0; k < 64; k++) {
        E2[k].x = __expf(tr[(2 * k)     * LL + j]);
        E2[k].y = __expf(tr[(2 * k + 1) * LL + j]);
    }

    // ---- sequence lengths (mask is a monotone prefix)
    if (j < 2) s_len[j] = 0;
    __syncthreads();
    {
        int cnt0 = 0, cnt1 = 0;
#pragma unroll
        for (int t = j; t < TT; t += 128) {
            cnt0 += (mask[b0 * TT + t] != 0) ? 1 : 0;
            cnt1 += (mask[b1 * TT + t] != 0) ? 1 : 0;
        }
        atomicAdd(&s_len[0], cnt0);
        atomicAdd(&s_len[1], cnt1);
    }
    __syncthreads();
    const int len0 = s_len[0];
    const int len1 = s_len[1];
    const int tmax = (len0 > len1) ? len0 : len1;

    // ---- gold path score (all 128 threads cooperate per batch)
    for (int b = 0; b < 2; b++) {
        const int bb = b0 + b;
        const int lb = (b == 0) ? len0 : len1;
        float gp = 0.0f;
        for (int t = j; t < lb; t += 128) {
            int tg   = tags[bb * TT + t];
            float e  = feat[(bb * TT + t) * LL + tg];
            int prev = (t == 0) ? BOSL : tags[bb * TT + t - 1];
            gp += e + tr[prev * LL + tg];
        }
#pragma unroll
        for (int o = 16; o > 0; o >>= 1) gp += __shfl_down_sync(0xffffffffu, gp, o);
        if (lane == 0) s_red[b][wid] = gp;
    }
    __syncthreads();
    if (j == 0) {
#pragma unroll
        for (int b = 0; b < 2; b++) {
            const int bb = b0 + b;
            const int lb = (b == 0) ? len0 : len1;
            float g = s_red[b][0] + s_red[b][1] + s_red[b][2] + s_red[b][3];
            g += tr[tags[bb * TT + lb - 1] * LL + EOSL];
            s_gold[b] = g;
        }
    }

    // ---- forward recursion init: fv = tr[BOS,:] + feat[:,0,:]
    const float trb = tr[BOSL * LL + j];
    float fv0 = trb + feat[(b0 * TT) * LL + j];
    float fv1 = trb + feat[(b1 * TT) * LL + j];
    if (j == 64) { c_sh[0][0] = fv0; c_sh[0][1] = fv1; }
    __syncthreads();
    float c0 = c_sh[0][0];
    float c1 = c_sh[0][1];

    float ft0 = 0.0f, ft1 = 0.0f;
    if (tmax > 1) {
        ft0 = feat[(b0 * TT + 1) * LL + j];
        ft1 = feat[(b1 * TT + 1) * LL + j];
    }

    int p = 0;
    for (int t = 1; t < tmax; t++) {
        // phase A: publish u = exp(fv - c) and the next normalizer (fv[64])
        float u0 = __expf(fv0 - c0);
        float u1 = __expf(fv1 - c1);
        u_sh[p][0][j] = u0;
        u_sh[p][1][j] = u1;
        if (j == 64) { c_sh[p][0] = fv0; c_sh[p][1] = fv1; }
        __syncthreads();
        float nc0 = c_sh[p][0];
        float nc1 = c_sh[p][1];

        // prefetch next step's emission row
        float nft0 = ft0, nft1 = ft1;
        if (t + 1 < tmax) {
            nft0 = feat[(b0 * TT + t + 1) * LL + j];
            nft1 = feat[(b1 * TT + t + 1) * LL + j];
        }

        // phase B: v[j] = sum_i u[i] * E[i][j]  (E in regs, u via LDS.128 broadcast)
        const float4* U0 = (const float4*)(u_sh[p][0]);
        const float4* U1 = (const float4*)(u_sh[p][1]);
        float2 va0 = make_float2(0.f, 0.f), vb0 = make_float2(0.f, 0.f);
        float2 va1 = make_float2(0.f, 0.f), vb1 = make_float2(0.f, 0.f);
#pragma unroll
        for (int k = 0; k < 32; k++) {
            float4 a = U0[k];
            float4 b = U1[k];
            va0 = ffma2(make_float2(a.x, a.y), E2[2 * k],     va0);
            vb0 = ffma2(make_float2(a.z, a.w), E2[2 * k + 1], vb0);
            va1 = ffma2(make_float2(b.x, b.y), E2[2 * k],     va1);
            vb1 = ffma2(make_float2(b.z, b.w), E2[2 * k + 1], vb1);
        }
        float s0 = (va0.x + vb0.x) + (va0.y + vb0.y);
        float s1 = (va1.x + vb1.x) + (va1.y + vb1.y);

        if (t < len0) fv0 = ft0 + c0 + __logf(s0);
        if (t < len1) fv1 = ft1 + c1 + __logf(s1);
        c0 = nc0; c1 = nc1;
        ft0 = nft0; ft1 = nft1;
        p ^= 1;
    }

    // ---- logZ = logsumexp_j(fv[j] + tr[j][EOS]) and per-batch result
    {
        float te = tr[j * LL + EOSL];
        float e0 = __expf((fv0 + te) - c0);
        float e1 = __expf((fv1 + te) - c1);
#pragma unroll
        for (int o = 16; o > 0; o >>= 1) {
            e0 += __shfl_down_sync(0xffffffffu, e0, o);
            e1 += __shfl_down_sync(0xffffffffu, e1, o);
        }
        __syncthreads();
        if (lane == 0) { s_red[0][wid] = e0; s_red[1][wid] = e1; }
        __syncthreads();
        if (j == 0) {
            float z0 = s_red[0][0] + s_red[0][1] + s_red[0][2] + s_red[0][3];
            float z1 = s_red[1][0] + s_red[1][1] + s_red[1][2] + s_red[1][3];
            float logZ0 = c0 + __logf(z0);
            float logZ1 = c1 + __logf(z1);
            g_res[b0] = logZ0 - s_gold[0];
            g_res[b1] = logZ1 - s_gold[1];
        }
    }
}

// deterministic fixed-order mean over the 512 per-batch results
__global__ void crf_reduce(float* __restrict__ out) {
    __shared__ float s[BB];
    int t = threadIdx.x;
    s[t] = g_res[t];
    __syncthreads();
#pragma unroll
    for (int k = BB / 2; k > 0; k >>= 1) {
        if (t < k) s[t] += s[t + k];
        __syncthreads();
    }
    if (t == 0) out[0] = s[0] * (1.0f / (float)BB);
}

extern "C" void kernel_launch(void* const* d_in, const int* in_sizes, int n_in,
                              void* d_out, int out_size) {
    const float* feat = (const float*)d_in[0];
    const int*   tags = (const int*)d_in[1];
    const int*   mask = (const int*)d_in[2];
    const float* tr   = (const float*)d_in[3];

    crf_fwd<<<BB / 2, 128>>>(feat, tags, mask, tr);
    crf_reduce<<<1, BB>>>((float*)d_out);
}